// round 15
// baseline (speedup 1.0000x reference)
#include <cuda_runtime.h>

#define NCLS 19
#define CH   256
#define HW   16384      // 128*128
#define BSZ  8
#define NQ   2975
#define INV_T 5.0f      // 1/0.2
#define LOG2E 1.44269504f

#define KCHUNK 64                 // pixel chunks per batch
#define CHUNK_PIX (HW/KCHUNK)     // 256
#define SUMS_BLOCKS (KCHUNK*BSZ)  // 512
#define NHALF 1488                // ceil(NQ/2)

#define PS     32                 // pixels per smem slice
#define NSLICE (CHUNK_PIX/PS)     // 8
#define TSTR   36                 // tile row stride (floats); 36%32=4 -> conflict-free LDS

// ---- device scratch. Protocol (kernel-boundary ordered, no tickets):
//  g_sums: zero at load; fused atomicAdds; keys reads; lse re-zeros.
//  g_lse : zero at load; lse atomicAdds; second-arriver reads+resets.
//  out_loss: keys zeroes; lse completers atomicAdd.
__device__ float g_sums[NCLS*CH];
__device__ float g_lse[NCLS*CH];
__device__ int   g_hist[SUMS_BLOCKS*NCLS];
__device__ int   g_counts[NCLS];
__device__ float g_keys[NCLS*CH];

__device__ __forceinline__ float ex2f(float x) {
    float r; asm("ex2.approx.f32 %0, %1;" : "=f"(r) : "f"(x)); return r;
}
__device__ __forceinline__ unsigned cvt_tf32(float x) {
    unsigned r; asm("cvt.rna.tf32.f32 %0, %1;" : "=r"(r) : "f"(x)); return r;
}
__device__ __forceinline__ void mma_tf32(float* d, const unsigned* a,
                                         unsigned b0, unsigned b1) {
    asm("mma.sync.aligned.m16n8k8.row.col.f32.tf32.tf32.f32 "
        "{%0,%1,%2,%3}, {%4,%5,%6,%7}, {%8,%9}, {%0,%1,%2,%3};"
        : "+f"(d[0]), "+f"(d[1]), "+f"(d[2]), "+f"(d[3])
        : "r"(a[0]), "r"(a[1]), "r"(a[2]), "r"(a[3]), "r"(b0), "r"(b1));
}

// ---------------------------------------------------------------------------
// fused pred + sums. Phase 1: argmax + res->out + hist. Phase 2: TF32 MMA
// pooling, fea staged per 32-px slice through smem:
//   global: LDG.128 fully coalesced (8 lanes x 128B contiguous per row)
//   smem  : row stride 36 floats -> compute LDS banks 4*gq+gr, conflict-free
// ---------------------------------------------------------------------------
__global__ void __launch_bounds__(256) fused_kernel(const float* __restrict__ res,
                                                    float* __restrict__ out,
                                                    const float* __restrict__ fea) {
    int b      = blockIdx.y;
    int chunk  = blockIdx.x;
    int p_base = chunk * CHUNK_PIX;
    int tid  = threadIdx.x;

    __shared__ float tile[CH * TSTR];          // 36 KB
    __shared__ unsigned char spred[CHUNK_PIX];
    __shared__ int hist[NCLS];
    if (tid < NCLS) hist[tid] = 0;
    __syncthreads();

    // ---- phase 1: pred for pixel p_base + tid ----
    {
        const float* r = res + (size_t)b * NCLS * HW + p_base + tid;
        float*       o = out + (size_t)b * NCLS * HW + p_base + tid;
        float best = r[0];
        o[0] = best;
        int bk = 0;
        #pragma unroll
        for (int k = 1; k < NCLS; k++) {
            float v = r[(size_t)k * HW];
            o[(size_t)k * HW] = v;
            if (v > best) { best = v; bk = k; }
        }
        spred[tid] = (unsigned char)bk;
        atomicAdd(&hist[bk], 1);
    }
    __syncthreads();
    if (tid < NCLS) g_hist[(b * KCHUNK + chunk) * NCLS + tid] = hist[tid];

    // ---- phase 2: smem-staged TF32 MMA pooling ----
    int warp = tid >> 5;
    int lane = tid & 31;
    int gq   = lane >> 2;
    int gr   = lane & 3;
    int c0   = warp * 32;

    float acc[2][4][4];
    #pragma unroll
    for (int mt = 0; mt < 2; mt++)
        #pragma unroll
        for (int nt = 0; nt < 4; nt++)
            #pragma unroll
            for (int i = 0; i < 4; i++) acc[mt][nt][i] = 0.0f;

    // loader role: 8 rows per thread; within a row, 8-lane groups are contiguous
    int ld_ch0 = tid >> 3;      // 0..31, +32*r
    int ld_f4  = tid & 7;       // float4 index in 32-px row
    const float* fb = fea + (size_t)b * CH * HW + p_base;

    // smem offsets used by compute (constant across slices)
    int tb[4];                  // tile base per nt: (c0 + nt*8 + gq) * TSTR
    #pragma unroll
    for (int nt = 0; nt < 4; nt++) tb[nt] = (c0 + nt * 8 + gq) * TSTR;

    for (int sl = 0; sl < NSLICE; sl++) {
        int px0 = sl * PS;
        // load 256ch x 32px slice
        #pragma unroll
        for (int r = 0; r < 8; r++) {
            int ch = r * 32 + ld_ch0;
            float4 v = *(const float4*)(fb + (size_t)ch * HW + px0 + ld_f4 * 4);
            *(float4*)(tile + ch * TSTR + ld_f4 * 4) = v;
        }
        __syncthreads();

        #pragma unroll
        for (int ksl = 0; ksl < PS / 8; ksl++) {
            int p = px0 + ksl * 8;
            int pk0 = spred[p + gr];
            int pk1 = spred[p + gr + 4];

            unsigned au[2][4];
            #pragma unroll
            for (int mt = 0; mt < 2; mt++) {
                int cls = mt * 16 + gq;
                au[mt][0] = (pk0 == cls)     ? 0x3f800000u : 0u;
                au[mt][1] = (pk0 == cls + 8) ? 0x3f800000u : 0u;
                au[mt][2] = (pk1 == cls)     ? 0x3f800000u : 0u;
                au[mt][3] = (pk1 == cls + 8) ? 0x3f800000u : 0u;
            }

            #pragma unroll
            for (int nt = 0; nt < 4; nt++) {
                float b0f = tile[tb[nt] + ksl * 8 + gr];
                float b1f = tile[tb[nt] + ksl * 8 + gr + 4];
                unsigned b0h = cvt_tf32(b0f);
                unsigned b1h = cvt_tf32(b1f);
                unsigned b0l = cvt_tf32(b0f - __uint_as_float(b0h));
                unsigned b1l = cvt_tf32(b1f - __uint_as_float(b1h));
                #pragma unroll
                for (int mt = 0; mt < 2; mt++) {
                    mma_tf32(acc[mt][nt], au[mt], b0h, b1h);
                    mma_tf32(acc[mt][nt], au[mt], b0l, b1l);
                }
            }
        }
        __syncthreads();
    }

    #pragma unroll
    for (int mt = 0; mt < 2; mt++)
        #pragma unroll
        for (int nt = 0; nt < 4; nt++)
            #pragma unroll
            for (int i = 0; i < 4; i++) {
                int cls = mt * 16 + gq + ((i >> 1) << 3);
                if (cls < NCLS) {
                    int ch = c0 + nt * 8 + 2 * gr + (i & 1);
                    atomicAdd(&g_sums[cls * CH + ch], acc[mt][nt][i]);
                }
            }
}

// ---------------------------------------------------------------------------
// keys: hist->counts, masked mean + L2 normalize. One block per class.
// Also zeroes out_loss (runs before lse).
// ---------------------------------------------------------------------------
__global__ void __launch_bounds__(256) keys_kernel(float* __restrict__ out_loss) {
    int k = blockIdx.x;
    int c = threadIdx.x;
    if (k == 0 && c == 0) *out_loss = 0.0f;

    __shared__ float red[8];
    __shared__ float snorm;
    __shared__ int   scnt;

    int h = 0;
    for (int i = c; i < SUMS_BLOCKS; i += 256) h += g_hist[i * NCLS + k];
    #pragma unroll
    for (int o = 16; o; o >>= 1) h += __shfl_xor_sync(0xffffffffu, h, o);
    if ((c & 31) == 0) red[c >> 5] = __int_as_float(h);
    __syncthreads();
    if (c == 0) {
        int t = 0;
        #pragma unroll
        for (int i = 0; i < 8; i++) t += __float_as_int(red[i]);
        g_counts[k] = t;
        scnt = max(t, 1);
    }
    __syncthreads();

    float v = g_sums[k * CH + c] / (float)scnt;

    float ss = v * v;
    #pragma unroll
    for (int o = 16; o; o >>= 1) ss += __shfl_xor_sync(0xffffffffu, ss, o);
    if ((c & 31) == 0) red[c >> 5] = ss;
    __syncthreads();
    if (c == 0) {
        float t = 0.0f;
        #pragma unroll
        for (int i = 0; i < 8; i++) t += red[i];
        snorm = fmaxf(sqrtf(t), 1e-12f);
    }
    __syncthreads();
    g_keys[k * CH + c] = v / snorm;
}

// ---------------------------------------------------------------------------
// lse + inline finalize: grid (CH, 2). Second-arriving block per (k,c)
// (atomicAdd old != 0; partials strictly positive) finalizes the loss term
// and resets the slot. Blocks (c<19, half=0) re-zero g_sums for next replay.
// ---------------------------------------------------------------------------
__global__ void __launch_bounds__(256) lse_kernel(const float* __restrict__ queues,
                                                  float* __restrict__ out_loss) {
    int c    = blockIdx.x;
    int half = blockIdx.y;
    int tid  = threadIdx.x;

    if (half == 0 && c < NCLS) g_sums[c * CH + tid] = 0.0f;

    __shared__ float sbb[NCLS];
    if (tid < NCLS) sbb[tid] = g_keys[tid * CH + c] * (INV_T * LOG2E);
    __syncthreads();

    float bb[NCLS];
    #pragma unroll
    for (int k = 0; k < NCLS; k++) bb[k] = sbb[k];

    const float* base = queues + (size_t)c * NQ;
    float s[NCLS];
    #pragma unroll
    for (int k = 0; k < NCLS; k++) s[k] = 0.0f;

    int jend = min(NQ, (half + 1) * NHALF);
    for (int j = half * NHALF + tid; j < jend; j += 256) {
        float q[NCLS];
        float qs = 0.0f;
        #pragma unroll
        for (int k = 0; k < NCLS; k++) {
            q[k] = base[(size_t)k * CH * NQ + j];
            qs += q[k];
        }
        #pragma unroll
        for (int k = 0; k < NCLS; k++) {
            float x = bb[k] * q[k];
            s[k] += ex2f(x) + ex2f(bb[k] * qs - x);
        }
    }

    __shared__ float wred[8][NCLS];
    int lane = tid & 31, wid = tid >> 5;
    #pragma unroll
    for (int k = 0; k < NCLS; k++) {
        float v = s[k];
        #pragma unroll
        for (int o = 16; o; o >>= 1) v += __shfl_xor_sync(0xffffffffu, v, o);
        if (lane == 0) wred[wid][k] = v;
    }
    __syncthreads();

    if (tid < 32) {
        float part = 0.0f;
        if (tid < NCLS) {
            float tot = 0.0f;
            #pragma unroll
            for (int w = 0; w < 8; w++) tot += wred[w][tid];
            float old = atomicAdd(&g_lse[tid * CH + c], tot);
            if (old != 0.0f) {                      // completer
                float full = old + tot;
                g_lse[tid * CH + c] = 0.0f;         // reset for next replay
                if (g_counts[tid] > 0) {
                    float a  = g_keys[tid * CH + c] * INV_T;
                    float q0 = queues[((size_t)(tid * CH + c)) * NQ];
                    part = (__logf(full) - a * q0) * (1.0f / (float)CH);
                }
            }
        }
        #pragma unroll
        for (int o = 16; o; o >>= 1) part += __shfl_xor_sync(0xffffffffu, part, o);
        if (tid == 0 && part != 0.0f) atomicAdd(out_loss, part);
    }
}

// ---------------------------------------------------------------------------
extern "C" void kernel_launch(void* const* d_in, const int* in_sizes, int n_in,
                              void* d_out, int out_size) {
    const float *fea = nullptr, *res = nullptr, *queues = nullptr;
    for (int i = 0; i < n_in; i++) {
        if (in_sizes[i] == BSZ * CH * HW)        fea    = (const float*)d_in[i];
        else if (in_sizes[i] == BSZ * NCLS * HW) res    = (const float*)d_in[i];
        else if (in_sizes[i] == NCLS * CH * NQ)  queues = (const float*)d_in[i];
    }
    float* out      = (float*)d_out;
    float* out_loss = out + (size_t)BSZ * NCLS * HW;

    fused_kernel<<<dim3(KCHUNK, BSZ), 256>>>(res, out, fea);
    keys_kernel<<<NCLS, 256>>>(out_loss);
    lse_kernel<<<dim3(CH, 2), 256>>>(queues, out_loss);
}